// round 14
// baseline (speedup 1.0000x reference)
#include <cuda_runtime.h>
#include <math.h>

#define BATCH   2048
#define NCH     128
#define TOTDIM  200

// Flattened offsets of the per-l A blocks: sizes 1,9,25,49,81 -> total 165
#define AOFF0 0
#define AOFF1 1
#define AOFF2 10
#define AOFF3 35
#define AOFF4 84
#define ATOT  165

struct AParams { float A[ATOT]; };   // constant Wigner A(l) blocks (kernel param)

// ---------------------------------------------------------------------------
// Host-side computation of the constant A(l) matrices (exact port of the
// Python reference, fp64). Runs at capture time only — zero replay cost.
// ---------------------------------------------------------------------------
static double h_fact(int n) {
    double r = 1.0;
    for (int k = 2; k <= n; ++k) r *= (double)k;
    return r;
}

static void host_compute_A(AParams& P) {
    const double PI = 3.14159265358979323846;
    const double IS2 = 0.70710678118654752440;
    int off = 0;
    for (int l = 0; l < 5; ++l) {
        int d = 2 * l + 1;
        double sd[9][9];
        double cb = cos(-PI / 4.0), sb = sin(-PI / 4.0);
        for (int mp = -l; mp <= l; ++mp) {
            for (int m = -l; m <= l; ++m) {
                double pref = sqrt(h_fact(l + mp) * h_fact(l - mp) *
                                   h_fact(l + m) * h_fact(l - m));
                double tot = 0.0;
                int s0 = (m - mp > 0) ? (m - mp) : 0;
                int s1 = (l + m < l - mp) ? (l + m) : (l - mp);
                for (int s = s0; s <= s1; ++s) {
                    double den = h_fact(l + m - s) * h_fact(s) *
                                 h_fact(mp - m + s) * h_fact(l - mp - s);
                    double sgn = ((mp - m + s) & 1) ? -1.0 : 1.0;
                    tot += sgn / den * pow(cb, 2 * l + m - mp - 2 * s)
                                     * pow(sb, mp - m + 2 * s);
                }
                sd[mp + l][m + l] = pref * tot;
            }
        }
        double DcRe[9][9], DcIm[9][9];
        for (int p = 0; p < d; ++p) {
            for (int q = 0; q < d; ++q) {
                double ang = (p - l) * (PI / 2.0) - (q - l) * (PI / 2.0);
                DcRe[p][q] = cos(ang) * sd[p][q];
                DcIm[p][q] = sin(ang) * sd[p][q];
            }
        }
        double URe[9][9] = {}, UIm[9][9] = {};
        URe[l][l] = 1.0;
        for (int m = 1; m <= l; ++m) {
            double sgn = (m & 1) ? -1.0 : 1.0;
            URe[l + m][l + m] = sgn * IS2;
            URe[l + m][l - m] = IS2;
            UIm[l - m][l - m] = IS2;
            UIm[l - m][l + m] = -sgn * IS2;
        }
        double TRe[9][9], TIm[9][9];
        for (int i = 0; i < d; ++i) {
            for (int q = 0; q < d; ++q) {
                double re = 0.0, im = 0.0;
                for (int p = 0; p < d; ++p) {
                    re += URe[i][p] * DcRe[p][q] - UIm[i][p] * DcIm[p][q];
                    im += URe[i][p] * DcIm[p][q] + UIm[i][p] * DcRe[p][q];
                }
                TRe[i][q] = re; TIm[i][q] = im;
            }
        }
        for (int i = 0; i < d; ++i) {
            for (int j = 0; j < d; ++j) {
                double a = 0.0;
                for (int q = 0; q < d; ++q)
                    a += TRe[i][q] * URe[j][q] + TIm[i][q] * UIm[j][q];
                P.A[off + i * d + j] = (float)a;
            }
        }
        off += d * d;
    }
}

// ---------------------------------------------------------------------------
// Z-rotation coefficient helpers on a per-batch global sincos row (10 floats:
// m=0..4 x {sin,cos}).
// ---------------------------------------------------------------------------
__device__ __forceinline__ float zcg(const float* g, int k, int L) {
    int am = (k >= L) ? (k - L) : (L - k);
    return __ldg(g + am * 2 + 1);
}
__device__ __forceinline__ float zsg(const float* g, int k, int L) {
    int mm = k - L;
    if (mm > 0) return  __ldg(g + mm * 2);
    if (mm < 0) return -__ldg(g - mm * 2);
    return 0.0f;
}

// One entry of D = Za * A * Zb * A^T * Zg, computed from the constant-bank A
// block and global (L1/L2-resident) sincos rows. No smem inputs.
template <int L>
__device__ __forceinline__ float build_entry_g(const float* alB, const float* beB,
                                               const float* gaB,
                                               const float* A, int e) {
    constexpr int D = 2 * L + 1;
    const int i = e / D, j = e - i * D;
    const int ri = D - 1 - i, rj = D - 1 - j;
    const float cg = zcg(gaB, j, L);
    const float sg = zsg(gaB, rj, L);
    float t3 = 0.0f, t3r = 0.0f;
#pragma unroll
    for (int k = 0; k < D; ++k) {
        const int rk = D - 1 - k;
        float T1k  = A[j * D + k]  * cg + A[rj * D + k]  * sg;
        float T1rk = A[j * D + rk] * cg + A[rj * D + rk] * sg;
        float T2k = zcg(beB, k, L) * T1k + zsg(beB, k, L) * T1rk;
        t3  = fmaf(A[i * D + k],  T2k, t3);
        t3r = fmaf(A[ri * D + k], T2k, t3r);
    }
    return zcg(alB, i, L) * t3 + zsg(alB, i, L) * t3r;
}

// ---------------------------------------------------------------------------
// Per-segment processing with exactly ONE barrier:
//   builders (tid < D*D) compute their D entry (ldg sincos + const-bank A),
//   everyone issues x loads (evict-first), builders publish to smem, one
//   sync, FMA + streaming store. Input and output are touched exactly once.
// ---------------------------------------------------------------------------
template <int L>
__device__ __forceinline__ void seg_full(const float* __restrict__ x,
                                         float* __restrict__ y,
                                         const float* __restrict__ Ablk,
                                         const float* alB, const float* beB,
                                         const float* gaB, float* DmS,
                                         int b, int OFF, int tid) {
    constexpr int D  = 2 * L + 1;
    constexpr int DD = D * D;
    const int mult = tid >> 5;
    const int lane = tid & 31;
    const size_t base = ((size_t)b * TOTDIM + OFF + mult * D) * NCH;
    const float4* xp = (const float4*)(x + base);
    float4* yp = (float4*)(y + base);

    // Builders start their sincos loads / ALU first (program order).
    float dval = 0.0f;
    if (tid < DD) dval = build_entry_g<L>(alB, beB, gaB, Ablk, tid);

    // Pre-issue global x loads (in flight across the barrier).
    float4 xr[D];
#pragma unroll
    for (int j = 0; j < D; ++j) xr[j] = __ldcs(xp + j * 32 + lane);

    if (tid < DD) DmS[tid] = dval;
    __syncthreads();

#pragma unroll
    for (int i = 0; i < D; ++i) {
        float4 acc = { 0.f, 0.f, 0.f, 0.f };
#pragma unroll
        for (int j = 0; j < D; ++j) {
            float c = DmS[i * D + j];
            acc.x = fmaf(c, xr[j].x, acc.x);
            acc.y = fmaf(c, xr[j].y, acc.y);
            acc.z = fmaf(c, xr[j].z, acc.z);
            acc.w = fmaf(c, xr[j].w, acc.w);
        }
        __stcs(yp + i * 32 + lane, acc);
    }
}

// ---------------------------------------------------------------------------
// Kernel: 1D grid of 8192 blocks, 256 threads, min 4 blocks/SM (<=64 regs).
//   type = blockIdx.x & 3   (0 -> l0+l1, 1 -> l2, 2 -> l3, 3 -> l4)
//   b    = blockIdx.x >> 2
// Interleaving types keeps every scheduling wave load-balanced and gives
// consecutive blocks same-batch locality.
// ---------------------------------------------------------------------------
__global__ void __launch_bounds__(256, 4)
fused_kernel(const AParams Ap,
             const float* __restrict__ x,
             const float* __restrict__ al,
             const float* __restrict__ be,
             const float* __restrict__ ga,
             float* __restrict__ y) {
    const int bx   = blockIdx.x;
    const int b    = bx >> 2;
    const int type = bx & 3;
    const int tid  = threadIdx.x;

    __shared__ float DmS[81];

    const float* alB = al + b * 10;
    const float* beB = be + b * 10;
    const float* gaB = ga + b * 10;

    switch (type) {
        case 0: {  // l=0 (rows 0..7) + l=1 (rows 8..31)
            const int mult = tid >> 5;
            const int lane = tid & 31;
            const size_t base0 = ((size_t)b * TOTDIM + mult) * NCH;
            const size_t base1 = ((size_t)b * TOTDIM + 8 + mult * 3) * NCH;
            const float4* xp0 = (const float4*)(x + base0);
            const float4* xp1 = (const float4*)(x + base1);

            // builders first
            float dval = 0.0f;
            if (tid == 0)      dval = build_entry_g<0>(alB, beB, gaB, Ap.A + AOFF0, 0);
            else if (tid < 10) dval = build_entry_g<1>(alB, beB, gaB, Ap.A + AOFF1, tid - 1);

            // pre-issue loads
            float4 x0 = __ldcs(xp0 + lane);
            float4 xr[3];
#pragma unroll
            for (int j = 0; j < 3; ++j) xr[j] = __ldcs(xp1 + j * 32 + lane);

            if (tid < 10) DmS[tid] = dval;
            __syncthreads();

            {   // l=0
                float c = DmS[0];
                float4* yp0 = (float4*)(y + base0);
                float4 r = { c * x0.x, c * x0.y, c * x0.z, c * x0.w };
                __stcs(yp0 + lane, r);
            }
            {   // l=1
                float4* yp1 = (float4*)(y + base1);
#pragma unroll
                for (int i = 0; i < 3; ++i) {
                    float4 acc = { 0.f, 0.f, 0.f, 0.f };
#pragma unroll
                    for (int j = 0; j < 3; ++j) {
                        float c = DmS[1 + i * 3 + j];
                        acc.x = fmaf(c, xr[j].x, acc.x);
                        acc.y = fmaf(c, xr[j].y, acc.y);
                        acc.z = fmaf(c, xr[j].z, acc.z);
                        acc.w = fmaf(c, xr[j].w, acc.w);
                    }
                    __stcs(yp1 + i * 32 + lane, acc);
                }
            }
            break;
        }
        case 1: seg_full<2>(x, y, Ap.A + AOFF2, alB, beB, gaB, DmS, b, 32,  tid); break;
        case 2: seg_full<3>(x, y, Ap.A + AOFF3, alB, beB, gaB, DmS, b, 72,  tid); break;
        default: seg_full<4>(x, y, Ap.A + AOFF4, alB, beB, gaB, DmS, b, 128, tid); break;
    }
}

// ---------------------------------------------------------------------------
extern "C" void kernel_launch(void* const* d_in, const int* in_sizes, int n_in,
                              void* d_out, int out_size) {
    (void)in_sizes; (void)n_in; (void)out_size;
    const float* x  = (const float*)d_in[0];  // (2048, 200, 128) f32
    const float* al = (const float*)d_in[1];  // (2048, 5, 2) f32
    const float* be = (const float*)d_in[2];
    const float* ga = (const float*)d_in[3];
    float* y = (float*)d_out;

    AParams P;
    host_compute_A(P);   // host-side, capture-time only

    fused_kernel<<<BATCH * 4, 256>>>(P, x, al, be, ga, y);
}

// round 15
// speedup vs baseline: 1.0353x; 1.0353x over previous
#include <cuda_runtime.h>
#include <math.h>

#define BATCH   2048
#define NCH     128
#define TOTDIM  200

// Flattened offsets of the per-l A blocks: sizes 1,9,25,49,81 -> total 165
#define AOFF0 0
#define AOFF1 1
#define AOFF2 10
#define AOFF3 35
#define AOFF4 84
#define ATOT  165

struct AParams { float A[ATOT]; };   // constant Wigner A(l) blocks (kernel param)

// ---------------------------------------------------------------------------
// Host-side computation of the constant A(l) matrices (exact port of the
// Python reference, fp64). Runs at capture time only — zero replay cost.
// ---------------------------------------------------------------------------
static double h_fact(int n) {
    double r = 1.0;
    for (int k = 2; k <= n; ++k) r *= (double)k;
    return r;
}

static void host_compute_A(AParams& P) {
    const double PI = 3.14159265358979323846;
    const double IS2 = 0.70710678118654752440;
    int off = 0;
    for (int l = 0; l < 5; ++l) {
        int d = 2 * l + 1;
        double sd[9][9];
        double cb = cos(-PI / 4.0), sb = sin(-PI / 4.0);
        for (int mp = -l; mp <= l; ++mp) {
            for (int m = -l; m <= l; ++m) {
                double pref = sqrt(h_fact(l + mp) * h_fact(l - mp) *
                                   h_fact(l + m) * h_fact(l - m));
                double tot = 0.0;
                int s0 = (m - mp > 0) ? (m - mp) : 0;
                int s1 = (l + m < l - mp) ? (l + m) : (l - mp);
                for (int s = s0; s <= s1; ++s) {
                    double den = h_fact(l + m - s) * h_fact(s) *
                                 h_fact(mp - m + s) * h_fact(l - mp - s);
                    double sgn = ((mp - m + s) & 1) ? -1.0 : 1.0;
                    tot += sgn / den * pow(cb, 2 * l + m - mp - 2 * s)
                                     * pow(sb, mp - m + 2 * s);
                }
                sd[mp + l][m + l] = pref * tot;
            }
        }
        double DcRe[9][9], DcIm[9][9];
        for (int p = 0; p < d; ++p) {
            for (int q = 0; q < d; ++q) {
                double ang = (p - l) * (PI / 2.0) - (q - l) * (PI / 2.0);
                DcRe[p][q] = cos(ang) * sd[p][q];
                DcIm[p][q] = sin(ang) * sd[p][q];
            }
        }
        double URe[9][9] = {}, UIm[9][9] = {};
        URe[l][l] = 1.0;
        for (int m = 1; m <= l; ++m) {
            double sgn = (m & 1) ? -1.0 : 1.0;
            URe[l + m][l + m] = sgn * IS2;
            URe[l + m][l - m] = IS2;
            UIm[l - m][l - m] = IS2;
            UIm[l - m][l + m] = -sgn * IS2;
        }
        double TRe[9][9], TIm[9][9];
        for (int i = 0; i < d; ++i) {
            for (int q = 0; q < d; ++q) {
                double re = 0.0, im = 0.0;
                for (int p = 0; p < d; ++p) {
                    re += URe[i][p] * DcRe[p][q] - UIm[i][p] * DcIm[p][q];
                    im += URe[i][p] * DcIm[p][q] + UIm[i][p] * DcRe[p][q];
                }
                TRe[i][q] = re; TIm[i][q] = im;
            }
        }
        for (int i = 0; i < d; ++i) {
            for (int j = 0; j < d; ++j) {
                double a = 0.0;
                for (int q = 0; q < d; ++q)
                    a += TRe[i][q] * URe[j][q] + TIm[i][q] * UIm[j][q];
                P.A[off + i * d + j] = (float)a;
            }
        }
        off += d * d;
    }
}

// ---------------------------------------------------------------------------
// Z-rotation coefficient helpers on a per-batch global sincos row (10 floats:
// m=0..4 x {sin,cos}).
// ---------------------------------------------------------------------------
__device__ __forceinline__ float zcg(const float* g, int k, int L) {
    int am = (k >= L) ? (k - L) : (L - k);
    return __ldg(g + am * 2 + 1);
}
__device__ __forceinline__ float zsg(const float* g, int k, int L) {
    int mm = k - L;
    if (mm > 0) return  __ldg(g + mm * 2);
    if (mm < 0) return -__ldg(g - mm * 2);
    return 0.0f;
}

// One entry of D = Za * A * Zb * A^T * Zg, computed from the constant-bank A
// block and global (L1/L2-resident) sincos rows. No smem inputs.
template <int L>
__device__ __forceinline__ float build_entry_g(const float* alB, const float* beB,
                                               const float* gaB,
                                               const float* A, int e) {
    constexpr int D = 2 * L + 1;
    const int i = e / D, j = e - i * D;
    const int ri = D - 1 - i, rj = D - 1 - j;
    const float cg = zcg(gaB, j, L);
    const float sg = zsg(gaB, rj, L);
    float t3 = 0.0f, t3r = 0.0f;
#pragma unroll
    for (int k = 0; k < D; ++k) {
        const int rk = D - 1 - k;
        float T1k  = A[j * D + k]  * cg + A[rj * D + k]  * sg;
        float T1rk = A[j * D + rk] * cg + A[rj * D + rk] * sg;
        float T2k = zcg(beB, k, L) * T1k + zsg(beB, k, L) * T1rk;
        t3  = fmaf(A[i * D + k],  T2k, t3);
        t3r = fmaf(A[ri * D + k], T2k, t3r);
    }
    return zcg(alB, i, L) * t3 + zsg(alB, i, L) * t3r;
}

// ---------------------------------------------------------------------------
// Per-segment processing with exactly ONE barrier:
//   builders (tid < D*D) compute their D entry (ldg sincos + const-bank A),
//   everyone issues x loads (evict-first), builders publish to smem, one
//   sync, FMA + streaming store. Input and output are touched exactly once.
// ---------------------------------------------------------------------------
template <int L>
__device__ __forceinline__ void seg_full(const float* __restrict__ x,
                                         float* __restrict__ y,
                                         const float* __restrict__ Ablk,
                                         const float* alB, const float* beB,
                                         const float* gaB, float* DmS,
                                         int b, int OFF, int tid) {
    constexpr int D  = 2 * L + 1;
    constexpr int DD = D * D;
    const int mult = tid >> 5;
    const int lane = tid & 31;
    const size_t base = ((size_t)b * TOTDIM + OFF + mult * D) * NCH;
    const float4* xp = (const float4*)(x + base);
    float4* yp = (float4*)(y + base);

    // Builders start their sincos loads / ALU first (program order).
    float dval = 0.0f;
    if (tid < DD) dval = build_entry_g<L>(alB, beB, gaB, Ablk, tid);

    // Pre-issue global x loads (in flight across the barrier).
    float4 xr[D];
#pragma unroll
    for (int j = 0; j < D; ++j) xr[j] = __ldcs(xp + j * 32 + lane);

    if (tid < DD) DmS[tid] = dval;
    __syncthreads();

#pragma unroll
    for (int i = 0; i < D; ++i) {
        float4 acc = { 0.f, 0.f, 0.f, 0.f };
#pragma unroll
        for (int j = 0; j < D; ++j) {
            float c = DmS[i * D + j];
            acc.x = fmaf(c, xr[j].x, acc.x);
            acc.y = fmaf(c, xr[j].y, acc.y);
            acc.z = fmaf(c, xr[j].z, acc.z);
            acc.w = fmaf(c, xr[j].w, acc.w);
        }
        __stcs(yp + i * 32 + lane, acc);
    }
}

// ---------------------------------------------------------------------------
// Kernel: 1D grid of 8192 blocks, 256 threads. No occupancy cap — R14 showed
// forcing 4 blocks/SM (64 regs) spills xr[] to local and regresses.
//   type = blockIdx.x & 3   (0 -> l0+l1, 1 -> l2, 2 -> l3, 3 -> l4)
//   b    = blockIdx.x >> 2
// ---------------------------------------------------------------------------
__global__ void __launch_bounds__(256)
fused_kernel(const AParams Ap,
             const float* __restrict__ x,
             const float* __restrict__ al,
             const float* __restrict__ be,
             const float* __restrict__ ga,
             float* __restrict__ y) {
    const int bx   = blockIdx.x;
    const int b    = bx >> 2;
    const int type = bx & 3;
    const int tid  = threadIdx.x;

    __shared__ float DmS[81];

    const float* alB = al + b * 10;
    const float* beB = be + b * 10;
    const float* gaB = ga + b * 10;

    switch (type) {
        case 0: {  // l=0 (rows 0..7) + l=1 (rows 8..31)
            const int mult = tid >> 5;
            const int lane = tid & 31;
            const size_t base0 = ((size_t)b * TOTDIM + mult) * NCH;
            const size_t base1 = ((size_t)b * TOTDIM + 8 + mult * 3) * NCH;
            const float4* xp0 = (const float4*)(x + base0);
            const float4* xp1 = (const float4*)(x + base1);

            // builders first
            float dval = 0.0f;
            if (tid == 0)      dval = build_entry_g<0>(alB, beB, gaB, Ap.A + AOFF0, 0);
            else if (tid < 10) dval = build_entry_g<1>(alB, beB, gaB, Ap.A + AOFF1, tid - 1);

            // pre-issue loads
            float4 x0 = __ldcs(xp0 + lane);
            float4 xr[3];
#pragma unroll
            for (int j = 0; j < 3; ++j) xr[j] = __ldcs(xp1 + j * 32 + lane);

            if (tid < 10) DmS[tid] = dval;
            __syncthreads();

            {   // l=0
                float c = DmS[0];
                float4* yp0 = (float4*)(y + base0);
                float4 r = { c * x0.x, c * x0.y, c * x0.z, c * x0.w };
                __stcs(yp0 + lane, r);
            }
            {   // l=1
                float4* yp1 = (float4*)(y + base1);
#pragma unroll
                for (int i = 0; i < 3; ++i) {
                    float4 acc = { 0.f, 0.f, 0.f, 0.f };
#pragma unroll
                    for (int j = 0; j < 3; ++j) {
                        float c = DmS[1 + i * 3 + j];
                        acc.x = fmaf(c, xr[j].x, acc.x);
                        acc.y = fmaf(c, xr[j].y, acc.y);
                        acc.z = fmaf(c, xr[j].z, acc.z);
                        acc.w = fmaf(c, xr[j].w, acc.w);
                    }
                    __stcs(yp1 + i * 32 + lane, acc);
                }
            }
            break;
        }
        case 1: seg_full<2>(x, y, Ap.A + AOFF2, alB, beB, gaB, DmS, b, 32,  tid); break;
        case 2: seg_full<3>(x, y, Ap.A + AOFF3, alB, beB, gaB, DmS, b, 72,  tid); break;
        default: seg_full<4>(x, y, Ap.A + AOFF4, alB, beB, gaB, DmS, b, 128, tid); break;
    }
}

// ---------------------------------------------------------------------------
extern "C" void kernel_launch(void* const* d_in, const int* in_sizes, int n_in,
                              void* d_out, int out_size) {
    (void)in_sizes; (void)n_in; (void)out_size;
    const float* x  = (const float*)d_in[0];  // (2048, 200, 128) f32
    const float* al = (const float*)d_in[1];  // (2048, 5, 2) f32
    const float* be = (const float*)d_in[2];
    const float* ga = (const float*)d_in[3];
    float* y = (float*)d_out;

    AParams P;
    host_compute_A(P);   // host-side, capture-time only

    fused_kernel<<<BATCH * 4, 256>>>(P, x, al, be, ga, y);
}